// round 7
// baseline (speedup 1.0000x reference)
#include <cuda_runtime.h>

// CorrAttentionBias: out[b,h,i,j] = attn + alpha*edge + beta*cs_i*cs_j, masked to NEG.
// B=2, H=16, L=2048. DRAM-roofline-bound streaming kernel.
// Persistent grid-stride variant: 148*8 CTAs each loop over ~55 rows,
// removing per-CTA dispatch churn and keeping load queues deep across rows.
// Mask dtype is int32 (proven on this dataset).

#define ALPHA 0.5f
#define BETA  0.1f
#define NEGV  -100000.0f

namespace {
constexpr int B = 2;
constexpr int H = 16;
constexpr int L = 2048;
constexpr int THREADS = 256;
constexpr int V4_PER_ROW = L / 4;                 // 512
constexpr int K_ITERS = V4_PER_ROW / THREADS;     // 2
constexpr int NROWS = B * H * L;                  // 65536
constexpr int GRID = 148 * 8;                     // persistent CTAs
}

__global__ __launch_bounds__(THREADS) void corr_bias_kernel(
    const float* __restrict__ attn,
    const float* __restrict__ c_local,
    const float* __restrict__ c_sink,
    const int* __restrict__ mask,     // int32 per element
    float* __restrict__ out)
{
    const int t = threadIdx.x;

    for (unsigned r = blockIdx.x; r < NROWS; r += GRID) {
        const int i = r & (L - 1);
        const int b = r >> 15;                    // H*L = 32768
        const long long base = (long long)r * L;

        float4* __restrict__ o4 = reinterpret_cast<float4*>(out + base);

        // Fully-masked row: write-only fast path (saves ~50% of attn reads).
        if (mask[b * L + i]) {
            const float4 neg = make_float4(NEGV, NEGV, NEGV, NEGV);
            #pragma unroll
            for (int k = 0; k < K_ITERS; k++)
                o4[t + k * THREADS] = neg;
            continue;
        }

        const float4* __restrict__ a4  = reinterpret_cast<const float4*>(attn + base);
        const float4* __restrict__ cs4 = reinterpret_cast<const float4*>(c_sink + b * L);
        const int4*   __restrict__ mi4 = reinterpret_cast<const int4*>(mask + b * L);

        const float csi = BETA * c_sink[b * L + i];

        // Neighbor bias values (reference overwrite semantics):
        //   j = i+1 : alpha * c_local[b, i+1]                     (i <= L-2)
        //   j = i-1 : alpha * c_local[b, i-1]  if 2 <= i <= L-2
        //             alpha * c_local[b, i]    if i == 1 or i == L-1
        float nl = 0.f, nr = 0.f;
        if (i >= 1) {
            nl = (i >= 2 && i <= L - 2) ? ALPHA * c_local[b * L + i - 1]
                                        : ALPHA * c_local[b * L + i];
        }
        if (i <= L - 2) {
            nr = ALPHA * c_local[b * L + i + 1];
        }

        #pragma unroll
        for (int k = 0; k < K_ITERS; k++) {
            const int v = t + k * THREADS;        // float4 index within row
            const int j = v * 4;

            const float4 a  = a4[v];
            const float4 cs = cs4[v];
            const int4   m  = mi4[v];

            float o0 = fmaf(csi, cs.x, a.x);
            float o1 = fmaf(csi, cs.y, a.y);
            float o2 = fmaf(csi, cs.z, a.z);
            float o3 = fmaf(csi, cs.w, a.w);

            // neighbor diagonals (at most one lane per vector hits)
            if (j - 3 <= i + 1 && i - 1 <= j + 3) {
                if (j + 0 == i - 1) o0 += nl; else if (j + 0 == i + 1) o0 += nr;
                if (j + 1 == i - 1) o1 += nl; else if (j + 1 == i + 1) o1 += nr;
                if (j + 2 == i - 1) o2 += nl; else if (j + 2 == i + 1) o2 += nr;
                if (j + 3 == i - 1) o3 += nl; else if (j + 3 == i + 1) o3 += nr;
            }

            if (m.x) o0 = NEGV;
            if (m.y) o1 = NEGV;
            if (m.z) o2 = NEGV;
            if (m.w) o3 = NEGV;

            o4[v] = make_float4(o0, o1, o2, o3);
        }
    }
}

extern "C" void kernel_launch(void* const* d_in, const int* in_sizes, int n_in,
                              void* d_out, int out_size)
{
    const float* attn    = (const float*)d_in[0];
    const float* c_local = (const float*)d_in[1];
    const float* c_sink  = (const float*)d_in[2];
    const int*   mask    = (const int*)d_in[3];
    float*       out     = (float*)d_out;

    corr_bias_kernel<<<GRID, THREADS>>>(attn, c_local, c_sink, mask, out);
}

// round 8
// speedup vs baseline: 1.0101x; 1.0101x over previous
#include <cuda_runtime.h>

// CorrAttentionBias: out[b,h,i,j] = attn + alpha*edge + beta*cs_i*cs_j, masked to NEG.
// B=2, H=16, L=2048. DRAM-roofline-bound (measured ceiling ~6.4 TB/s, 81% of spec,
// across 4 structural variants). This is the leanest variant: one row per block,
// 512 threads, exactly one float4 per thread (no inner loop).
// Masked rows (~50%) skip the attn read entirely.
// Mask dtype is int32 (proven on this dataset).

#define ALPHA 0.5f
#define BETA  0.1f
#define NEGV  -100000.0f

namespace {
constexpr int B = 2;
constexpr int H = 16;
constexpr int L = 2048;
constexpr int THREADS = 512;   // 512 * 4 floats = 2048 = one full row
}

__global__ __launch_bounds__(THREADS) void corr_bias_kernel(
    const float* __restrict__ attn,
    const float* __restrict__ c_local,
    const float* __restrict__ c_sink,
    const int* __restrict__ mask,     // int32 per element
    float* __restrict__ out)
{
    const unsigned r = blockIdx.x;            // r = (b*H + h)*L + i
    const int i = r & (L - 1);
    const int b = r >> 15;                    // H*L = 32768
    const long long base = (long long)r * L;
    const int v = threadIdx.x;                // float4 index within row
    const int j = v * 4;                      // first column of this chunk

    float4* __restrict__ o4 = reinterpret_cast<float4*>(out + base);

    // Fully-masked row: write-only fast path (saves ~50% of attn reads).
    if (mask[b * L + i]) {
        o4[v] = make_float4(NEGV, NEGV, NEGV, NEGV);
        return;
    }

    const float4* __restrict__ a4  = reinterpret_cast<const float4*>(attn + base);
    const float4* __restrict__ cs4 = reinterpret_cast<const float4*>(c_sink + b * L);
    const int4*   __restrict__ mi4 = reinterpret_cast<const int4*>(mask + b * L);

    // Front-batched loads: attn from DRAM, column vectors from L1/L2.
    const float4 a  = a4[v];
    const float4 cs = cs4[v];
    const int4   m  = mi4[v];

    const float csi = BETA * c_sink[b * L + i];

    // Neighbor bias values, matching the reference's overwrite semantics:
    //   j = i+1 : alpha * c_local[b, i+1]                     (i <= L-2)
    //   j = i-1 : alpha * c_local[b, i-1]  if 2 <= i <= L-2
    //             alpha * c_local[b, i]    if i == 1 or i == L-1
    float nl = 0.f, nr = 0.f;
    if (i >= 1) {
        nl = (i >= 2 && i <= L - 2) ? ALPHA * c_local[b * L + i - 1]
                                    : ALPHA * c_local[b * L + i];
    }
    if (i <= L - 2) {
        nr = ALPHA * c_local[b * L + i + 1];
    }

    float o0 = fmaf(csi, cs.x, a.x);
    float o1 = fmaf(csi, cs.y, a.y);
    float o2 = fmaf(csi, cs.z, a.z);
    float o3 = fmaf(csi, cs.w, a.w);

    // Neighbor diagonals (at most one lane per vector hits; cheap uniform reject).
    if (j - 3 <= i + 1 && i - 1 <= j + 3) {
        if (j + 0 == i - 1) o0 += nl; else if (j + 0 == i + 1) o0 += nr;
        if (j + 1 == i - 1) o1 += nl; else if (j + 1 == i + 1) o1 += nr;
        if (j + 2 == i - 1) o2 += nl; else if (j + 2 == i + 1) o2 += nr;
        if (j + 3 == i - 1) o3 += nl; else if (j + 3 == i + 1) o3 += nr;
    }

    if (m.x) o0 = NEGV;
    if (m.y) o1 = NEGV;
    if (m.z) o2 = NEGV;
    if (m.w) o3 = NEGV;

    o4[v] = make_float4(o0, o1, o2, o3);
}

extern "C" void kernel_launch(void* const* d_in, const int* in_sizes, int n_in,
                              void* d_out, int out_size)
{
    const float* attn    = (const float*)d_in[0];
    const float* c_local = (const float*)d_in[1];
    const float* c_sink  = (const float*)d_in[2];
    const int*   mask    = (const int*)d_in[3];
    float*       out     = (float*)d_out;

    const int grid = B * H * L;  // 65536 row-blocks
    corr_bias_kernel<<<grid, THREADS>>>(attn, c_local, c_sink, mask, out);
}

// round 9
// speedup vs baseline: 1.2080x; 1.1960x over previous
#include <cuda_runtime.h>

// CorrAttentionBias: out[b,h,i,j] = attn + alpha*edge + beta*cs_i*cs_j, masked to NEG.
// B=2, H=16, L=2048. DRAM-roofline-bound streaming kernel.
// MLP is the controlling variable (1/thr -> 62% DRAM, 2/thr -> 81%):
// this variant uses 128 threads x 4 float4/thread (one row per block) for
// 4-deep front-batched attn loads without R5's register/occupancy cost.
// Masked rows (~50%) skip the attn read entirely.
// Mask dtype is int32 (proven on this dataset).

#define ALPHA 0.5f
#define BETA  0.1f
#define NEGV  -100000.0f

namespace {
constexpr int B = 2;
constexpr int H = 16;
constexpr int L = 2048;
constexpr int THREADS = 128;                      // 128 * 4 * 4 = 2048 = one row
constexpr int K_ITERS = (L / 4) / THREADS;        // 4 float4 per thread
}

__global__ __launch_bounds__(THREADS) void corr_bias_kernel(
    const float* __restrict__ attn,
    const float* __restrict__ c_local,
    const float* __restrict__ c_sink,
    const int* __restrict__ mask,     // int32 per element
    float* __restrict__ out)
{
    const unsigned r = blockIdx.x;            // r = (b*H + h)*L + i
    const int i = r & (L - 1);
    const int b = r >> 15;                    // H*L = 32768
    const long long base = (long long)r * L;
    const int t = threadIdx.x;

    float4* __restrict__ o4 = reinterpret_cast<float4*>(out + base);

    // Fully-masked row: write-only fast path (saves ~50% of attn reads).
    if (mask[b * L + i]) {
        const float4 neg = make_float4(NEGV, NEGV, NEGV, NEGV);
        #pragma unroll
        for (int k = 0; k < K_ITERS; k++)
            o4[t + k * THREADS] = neg;
        return;
    }

    const float4* __restrict__ a4  = reinterpret_cast<const float4*>(attn + base);
    const float4* __restrict__ cs4 = reinterpret_cast<const float4*>(c_sink + b * L);
    const int4*   __restrict__ mi4 = reinterpret_cast<const int4*>(mask + b * L);

    // Front-batch ALL attn loads first: 4 independent LDG.128 in flight
    // before any dependent math (deep MLP hides DRAM latency).
    float4 a[K_ITERS];
    #pragma unroll
    for (int k = 0; k < K_ITERS; k++)
        a[k] = a4[t + k * THREADS];

    const float csi = BETA * c_sink[b * L + i];

    // Neighbor bias values, matching the reference's overwrite semantics:
    //   j = i+1 : alpha * c_local[b, i+1]                     (i <= L-2)
    //   j = i-1 : alpha * c_local[b, i-1]  if 2 <= i <= L-2
    //             alpha * c_local[b, i]    if i == 1 or i == L-1
    float nl = 0.f, nr = 0.f;
    if (i >= 1) {
        nl = (i >= 2 && i <= L - 2) ? ALPHA * c_local[b * L + i - 1]
                                    : ALPHA * c_local[b * L + i];
    }
    if (i <= L - 2) {
        nr = ALPHA * c_local[b * L + i + 1];
    }

    #pragma unroll
    for (int k = 0; k < K_ITERS; k++) {
        const int v = t + k * THREADS;        // float4 index within row
        const int j = v * 4;

        const float4 cs = cs4[v];             // L1/L2-resident column vectors
        const int4   m  = mi4[v];

        float o0 = fmaf(csi, cs.x, a[k].x);
        float o1 = fmaf(csi, cs.y, a[k].y);
        float o2 = fmaf(csi, cs.z, a[k].z);
        float o3 = fmaf(csi, cs.w, a[k].w);

        // neighbor diagonals (at most one lane per vector hits)
        if (j - 3 <= i + 1 && i - 1 <= j + 3) {
            if (j + 0 == i - 1) o0 += nl; else if (j + 0 == i + 1) o0 += nr;
            if (j + 1 == i - 1) o1 += nl; else if (j + 1 == i + 1) o1 += nr;
            if (j + 2 == i - 1) o2 += nl; else if (j + 2 == i + 1) o2 += nr;
            if (j + 3 == i - 1) o3 += nl; else if (j + 3 == i + 1) o3 += nr;
        }

        if (m.x) o0 = NEGV;
        if (m.y) o1 = NEGV;
        if (m.z) o2 = NEGV;
        if (m.w) o3 = NEGV;

        o4[v] = make_float4(o0, o1, o2, o3);
    }
}

extern "C" void kernel_launch(void* const* d_in, const int* in_sizes, int n_in,
                              void* d_out, int out_size)
{
    const float* attn    = (const float*)d_in[0];
    const float* c_local = (const float*)d_in[1];
    const float* c_sink  = (const float*)d_in[2];
    const int*   mask    = (const int*)d_in[3];
    float*       out     = (float*)d_out;

    const int grid = B * H * L;  // 65536 row-blocks
    corr_bias_kernel<<<grid, THREADS>>>(attn, c_local, c_sink, mask, out);
}

// round 11
// speedup vs baseline: 1.2227x; 1.0122x over previous
#include <cuda_runtime.h>

// CorrAttentionBias: out[b,h,i,j] = attn + alpha*edge + beta*cs_i*cs_j, masked to NEG.
// B=2, H=16, L=2048. DRAM-roofline-bound streaming kernel — converged optimum.
// Design-matrix result (occ x MLP is the controlling product):
//   256thr x 2 float4/thr: occ 80%, MLP 2 -> 81% DRAM, 117us  <-- this kernel
//   all other probed configs (1/thr, 4/thr, 256-bit, paired, persistent) are worse.
// Masked rows (~50%) skip the attn read entirely; c_sink/mask columns are L1-resident.
// Mask dtype is int32 (proven on this dataset).

#define ALPHA 0.5f
#define BETA  0.1f
#define NEGV  -100000.0f

namespace {
constexpr int B = 2;
constexpr int H = 16;
constexpr int L = 2048;
constexpr int THREADS = 256;
constexpr int V4_PER_THREAD = (L / 4) / THREADS;  // 2
}

__global__ __launch_bounds__(THREADS) void corr_bias_kernel(
    const float* __restrict__ attn,
    const float* __restrict__ c_local,
    const float* __restrict__ c_sink,
    const int* __restrict__ mask,     // int32 per element
    float* __restrict__ out)
{
    const unsigned r = blockIdx.x;            // r = (b*H + h)*L + i
    const int i = r & (L - 1);
    const int b = r >> 15;                    // H*L = 32768
    const long long base = (long long)r * L;

    float4* __restrict__ o4 = reinterpret_cast<float4*>(out + base);

    // Fully-masked row: write-only fast path (saves ~50% of attn reads).
    if (mask[b * L + i]) {
        const float4 neg = make_float4(NEGV, NEGV, NEGV, NEGV);
        #pragma unroll
        for (int k = 0; k < V4_PER_THREAD; k++)
            o4[threadIdx.x + k * THREADS] = neg;
        return;
    }

    const float4* __restrict__ a4  = reinterpret_cast<const float4*>(attn + base);
    const float4* __restrict__ cs4 = reinterpret_cast<const float4*>(c_sink + b * L);
    const int4*   __restrict__ mi4 = reinterpret_cast<const int4*>(mask + b * L);

    const float csi = BETA * c_sink[b * L + i];

    // Neighbor bias values, matching the reference's overwrite semantics:
    //   j = i+1 : alpha * c_local[b, i+1]                     (i <= L-2)
    //   j = i-1 : alpha * c_local[b, i-1]  if 2 <= i <= L-2
    //             alpha * c_local[b, i]    if i == 1 or i == L-1
    float nl = 0.f, nr = 0.f;
    if (i >= 1) {
        nl = (i >= 2 && i <= L - 2) ? ALPHA * c_local[b * L + i - 1]
                                    : ALPHA * c_local[b * L + i];
    }
    if (i <= L - 2) {
        nr = ALPHA * c_local[b * L + i + 1];
    }

    #pragma unroll
    for (int k = 0; k < V4_PER_THREAD; k++) {
        const int v = threadIdx.x + k * THREADS;  // float4 index within row
        const int j = v * 4;

        const float4 a  = a4[v];
        const float4 cs = cs4[v];
        const int4   m  = mi4[v];

        float o0 = fmaf(csi, cs.x, a.x);
        float o1 = fmaf(csi, cs.y, a.y);
        float o2 = fmaf(csi, cs.z, a.z);
        float o3 = fmaf(csi, cs.w, a.w);

        // neighbor diagonals (at most one lane per vector hits)
        if (j - 3 <= i + 1 && i - 1 <= j + 3) {
            if (j + 0 == i - 1) o0 += nl; else if (j + 0 == i + 1) o0 += nr;
            if (j + 1 == i - 1) o1 += nl; else if (j + 1 == i + 1) o1 += nr;
            if (j + 2 == i - 1) o2 += nl; else if (j + 2 == i + 1) o2 += nr;
            if (j + 3 == i - 1) o3 += nl; else if (j + 3 == i + 1) o3 += nr;
        }

        if (m.x) o0 = NEGV;
        if (m.y) o1 = NEGV;
        if (m.z) o2 = NEGV;
        if (m.w) o3 = NEGV;

        o4[v] = make_float4(o0, o1, o2, o3);
    }
}

extern "C" void kernel_launch(void* const* d_in, const int* in_sizes, int n_in,
                              void* d_out, int out_size)
{
    const float* attn    = (const float*)d_in[0];
    const float* c_local = (const float*)d_in[1];
    const float* c_sink  = (const float*)d_in[2];
    const int*   mask    = (const int*)d_in[3];
    float*       out     = (float*)d_out;

    const int grid = B * H * L;  // 65536 row-blocks
    corr_bias_kernel<<<grid, THREADS>>>(attn, c_local, c_sink, mask, out);
}

// round 12
// speedup vs baseline: 1.2271x; 1.0036x over previous
#include <cuda_runtime.h>

// CorrAttentionBias: out[b,h,i,j] = attn + alpha*edge + beta*cs_i*cs_j, masked to NEG.
// B=2, H=16, L=2048. DRAM-roofline-bound streaming kernel.
// R4-optimal structure (256 thr x 2 float4/thr, occ 80%, MLP 2) with ONE clean
// change: evict-first cache hints (__ldcs/__stcs) on the touch-once attn/out
// streams — isolated A/B (R3 confounded these with probe-load overhead).
// Masked rows (~50%) skip the attn read entirely. Mask dtype int32 (proven).

#define ALPHA 0.5f
#define BETA  0.1f
#define NEGV  -100000.0f

namespace {
constexpr int B = 2;
constexpr int H = 16;
constexpr int L = 2048;
constexpr int THREADS = 256;
constexpr int V4_PER_THREAD = (L / 4) / THREADS;  // 2
}

__global__ __launch_bounds__(THREADS) void corr_bias_kernel(
    const float* __restrict__ attn,
    const float* __restrict__ c_local,
    const float* __restrict__ c_sink,
    const int* __restrict__ mask,     // int32 per element
    float* __restrict__ out)
{
    const unsigned r = blockIdx.x;            // r = (b*H + h)*L + i
    const int i = r & (L - 1);
    const int b = r >> 15;                    // H*L = 32768
    const long long base = (long long)r * L;

    float4* __restrict__ o4 = reinterpret_cast<float4*>(out + base);

    // Fully-masked row: write-only fast path (saves ~50% of attn reads).
    if (mask[b * L + i]) {
        const float4 neg = make_float4(NEGV, NEGV, NEGV, NEGV);
        #pragma unroll
        for (int k = 0; k < V4_PER_THREAD; k++)
            __stcs(&o4[threadIdx.x + k * THREADS], neg);   // streaming store
        return;
    }

    const float4* __restrict__ a4  = reinterpret_cast<const float4*>(attn + base);
    const float4* __restrict__ cs4 = reinterpret_cast<const float4*>(c_sink + b * L);
    const int4*   __restrict__ mi4 = reinterpret_cast<const int4*>(mask + b * L);

    const float csi = BETA * c_sink[b * L + i];

    // Neighbor bias values, matching the reference's overwrite semantics:
    //   j = i+1 : alpha * c_local[b, i+1]                     (i <= L-2)
    //   j = i-1 : alpha * c_local[b, i-1]  if 2 <= i <= L-2
    //             alpha * c_local[b, i]    if i == 1 or i == L-1
    float nl = 0.f, nr = 0.f;
    if (i >= 1) {
        nl = (i >= 2 && i <= L - 2) ? ALPHA * c_local[b * L + i - 1]
                                    : ALPHA * c_local[b * L + i];
    }
    if (i <= L - 2) {
        nr = ALPHA * c_local[b * L + i + 1];
    }

    #pragma unroll
    for (int k = 0; k < V4_PER_THREAD; k++) {
        const int v = threadIdx.x + k * THREADS;  // float4 index within row
        const int j = v * 4;

        const float4 a  = __ldcs(&a4[v]);         // touch-once read stream
        const float4 cs = cs4[v];                 // L1/L2-resident (default policy)
        const int4   m  = mi4[v];

        float o0 = fmaf(csi, cs.x, a.x);
        float o1 = fmaf(csi, cs.y, a.y);
        float o2 = fmaf(csi, cs.z, a.z);
        float o3 = fmaf(csi, cs.w, a.w);

        // neighbor diagonals (at most one lane per vector hits)
        if (j - 3 <= i + 1 && i - 1 <= j + 3) {
            if (j + 0 == i - 1) o0 += nl; else if (j + 0 == i + 1) o0 += nr;
            if (j + 1 == i - 1) o1 += nl; else if (j + 1 == i + 1) o1 += nr;
            if (j + 2 == i - 1) o2 += nl; else if (j + 2 == i + 1) o2 += nr;
            if (j + 3 == i - 1) o3 += nl; else if (j + 3 == i + 1) o3 += nr;
        }

        if (m.x) o0 = NEGV;
        if (m.y) o1 = NEGV;
        if (m.z) o2 = NEGV;
        if (m.w) o3 = NEGV;

        __stcs(&o4[v], make_float4(o0, o1, o2, o3));  // streaming store
    }
}

extern "C" void kernel_launch(void* const* d_in, const int* in_sizes, int n_in,
                              void* d_out, int out_size)
{
    const float* attn    = (const float*)d_in[0];
    const float* c_local = (const float*)d_in[1];
    const float* c_sink  = (const float*)d_in[2];
    const int*   mask    = (const int*)d_in[3];
    float*       out     = (float*)d_out;

    const int grid = B * H * L;  // 65536 row-blocks
    corr_bias_kernel<<<grid, THREADS>>>(attn, c_local, c_sink, mask, out);
}